// round 4
// baseline (speedup 1.0000x reference)
#include <cuda_runtime.h>
#include <cstdint>

#define NUM_A   98304
#define NUM_T   1024
#define NCLS    21
#define NLOGIT  (NUM_A * NCLS)          // 2064384
#define NVEC    (NLOGIT / 4)            // 516096 float4

#define BLK     128
#define APT     2
#define CHUNK   128
#define NCHUNK  8
#define AG      (NUM_A / (BLK * APT))   // 384 anchor groups
#define MATCH_UNITS (AG * NCHUNK)       // 3072
#define FOCAL_UNITS 256
#define VEC_PER_FU  (NVEC / FOCAL_UNITS)  // 2016
#define TOTAL_UNITS (FOCAL_UNITS + MATCH_UNITS)  // 3328
#define GRID    1184                    // 148 SMs * 8 resident blocks

#define EPI_BLK   256
#define EPI_GRID  (NUM_A / EPI_BLK)     // 384

typedef unsigned long long ull;

// ---------------- device-global scratch (zero-init; self-restoring) ----------
__device__ ull      g_apart[NCHUNK * NUM_A]; // plain stores, no init needed
__device__ ull      g_tkey[NUM_T];           // atomicMax; reset by last block
__device__ double   g_cls_sum;               // reset by last block
__device__ int      g_npos;                  // reset by last block
__device__ unsigned g_ticket;                // reset by last block

// fast negative-class focal: 0.75 * sigmoid(x)^2 * softplus(x) ; 3 MUFU ops
__device__ __forceinline__ float focal_neg(float x) {
    float u = exp2f(x * 1.4426950408889634f);   // e^x
    float d = u + 1.0f;
    float q; asm("rcp.approx.f32 %0, %1;" : "=f"(q) : "f"(d));
    float lg = __log2f(d);
    float p  = u * q;
    return (0.75f * 0.6931471805599453f) * (p * p) * lg;
}

// ---------------- fused persistent kernel: neg-focal + match ----------------
__global__ void __launch_bounds__(BLK) fused_kernel(
    const float* __restrict__ anchors,
    const float* __restrict__ tboxes,
    const float* __restrict__ cls_preds)
{
    __shared__ float4 s_tb[CHUNK];
    __shared__ float  s_ta[CHUNK];

    const int tid = threadIdx.x;
    float facc = 0.0f;
    bool  did_focal = false;

    for (int u = blockIdx.x; u < TOTAL_UNITS; u += GRID) {
        if (u < FOCAL_UNITS) {
            // ---- negative focal slice (match-independent bulk sum) ----------
            did_focal = true;
            const float4* cp = (const float4*)cls_preds;
            const int lo = u * VEC_PER_FU;
            const int hi = lo + VEC_PER_FU;
            for (int i = lo + tid; i < hi; i += BLK) {
                float4 v = cp[i];
                facc += focal_neg(v.x) + focal_neg(v.y)
                      + focal_neg(v.z) + focal_neg(v.w);
            }
            continue;
        }

        // ---- match unit: 256 anchors x 128 targets ---------------------------
        const int m = u - FOCAL_UNITS;
        const int g = m % AG;
        const int c = m / AG;
        const int tbase = c * CHUNK;

        __syncthreads();   // previous unit's smem readers done
        {
            float4 b = ((const float4*)tboxes)[tbase + tid];
            s_tb[tid] = b;
            s_ta[tid] = (b.z - b.x) * (b.w - b.y);
        }
        __syncthreads();

        const int a0 = g * (BLK * APT) + tid;
        float4 A0 = ((const float4*)anchors)[a0];
        float4 A1 = ((const float4*)anchors)[a0 + BLK];
        float area0 = (A0.z - A0.x) * (A0.w - A0.y);
        float area1 = (A1.z - A1.x) * (A1.w - A1.y);
        float bi0 = 0.0f, bS0 = 1.0f, bi1 = 0.0f, bS1 = 1.0f;
        int   bt0 = 0, bt1 = 0;

        #pragma unroll 4
        for (int t = 0; t < CHUNK; ++t) {
            const float4 tb = s_tb[t];
            const float  ta = s_ta[t];
            {
                float lx = fmaxf(A0.x, tb.x), ly = fmaxf(A0.y, tb.y);
                float rx = fminf(A0.z, tb.z), ry = fminf(A0.w, tb.w);
                float w  = fmaxf(rx - lx, 0.0f);
                float inter = w * (ry - ly);
                float S     = area0 + ta;
                bool p = inter * bS0 > bi0 * S;   // iou cross-mult compare
                bi0 = p ? inter : bi0;
                bS0 = p ? S     : bS0;
                bt0 = p ? t     : bt0;
                if (inter > 0.3103448f * S) {     // iou > 0.45, rare
                    float iou = __fdividef(inter, S - inter);
                    ull key = ((ull)__float_as_uint(iou) << 32)
                            | (ull)(0xFFFFFFFFu - (unsigned)a0);
                    atomicMax(&g_tkey[tbase + t], key);
                }
            }
            {
                float lx = fmaxf(A1.x, tb.x), ly = fmaxf(A1.y, tb.y);
                float rx = fminf(A1.z, tb.z), ry = fminf(A1.w, tb.w);
                float w  = fmaxf(rx - lx, 0.0f);
                float inter = w * (ry - ly);
                float S     = area1 + ta;
                bool p = inter * bS1 > bi1 * S;
                bi1 = p ? inter : bi1;
                bS1 = p ? S     : bS1;
                bt1 = p ? t     : bt1;
                if (inter > 0.3103448f * S) {
                    float iou = __fdividef(inter, S - inter);
                    ull key = ((ull)__float_as_uint(iou) << 32)
                            | (ull)(0xFFFFFFFFu - (unsigned)(a0 + BLK));
                    atomicMax(&g_tkey[tbase + t], key);
                }
            }
        }

        // plain coalesced slot stores — no init, no atomics
        {
            float iou0 = __fdividef(bi0, bS0 - bi0);
            g_apart[c * NUM_A + a0] =
                ((ull)__float_as_uint(iou0) << 32)
                | (ull)(0xFFFFFFFFu - (unsigned)(tbase + bt0));
            float iou1 = __fdividef(bi1, bS1 - bi1);
            g_apart[c * NUM_A + a0 + BLK] =
                ((ull)__float_as_uint(iou1) << 32)
                | (ull)(0xFFFFFFFFu - (unsigned)(tbase + bt1));
        }
    }

    // ---- focal partial reduction -------------------------------------------
    if (__syncthreads_or(did_focal)) {
        #pragma unroll
        for (int o = 16; o > 0; o >>= 1)
            facc += __shfl_down_sync(0xFFFFFFFFu, facc, o);
        __shared__ float rs[4];
        if ((tid & 31) == 0) rs[tid >> 5] = facc;
        __syncthreads();
        if (tid == 0)
            atomicAdd(&g_cls_sum, (double)(rs[0] + rs[1] + rs[2] + rs[3]));
    }
}

// ---------------- epilogue: merge + pos-focal + (last block) final ----------
__device__ __forceinline__ float sl1(float d) {
    float ad = fabsf(d);
    return (ad < 1.0f) ? 0.5f * d * d : ad - 0.5f;
}

__global__ void __launch_bounds__(EPI_BLK) epilogue_kernel(
    const float* __restrict__ cls_preds,
    const int*   __restrict__ tlabels,
    const float* __restrict__ boxes_preds,
    const float* __restrict__ anchors,
    const float* __restrict__ tboxes,
    float* __restrict__ out)
{
    const int tid = threadIdx.x;
    const int a = blockIdx.x * EPI_BLK + tid;

    // merge the 8 chunk partials for this anchor
    ull best = 0ULL;
    #pragma unroll
    for (int c = 0; c < NCHUNK; ++c) {
        ull k = g_apart[c * NUM_A + a];
        best = (k > best) ? k : best;
    }
    float iou = __uint_as_float((unsigned)(best >> 32));
    float delta = 0.0f;
    int   np = 0;
    if (iou >= 0.5f) {
        np = 1;
        int t = (int)(0xFFFFFFFFu - (unsigned)(best & 0xFFFFFFFFull));
        int L = tlabels[t];
        float x = cls_preds[(size_t)a * NCLS + L];
        float ax = fabsf(x);
        float ce = fmaxf(x, 0.0f) - x + log1pf(expf(-ax));
        float p  = 1.0f / (1.0f + expf(-x));
        float om = 1.0f - p;
        delta = 0.25f * om * om * ce - focal_neg(x);
    }
    #pragma unroll
    for (int o = 16; o > 0; o >>= 1) {
        delta += __shfl_down_sync(0xFFFFFFFFu, delta, o);
        np    += __shfl_down_sync(0xFFFFFFFFu, np,    o);
    }
    __shared__ float rs[8];
    __shared__ int   ri[8];
    if ((tid & 31) == 0) { rs[tid >> 5] = delta; ri[tid >> 5] = np; }
    __syncthreads();
    if (tid == 0) {
        float bs = 0.0f; int bn = 0;
        #pragma unroll
        for (int i = 0; i < 8; ++i) { bs += rs[i]; bn += ri[i]; }
        atomicAdd(&g_cls_sum, (double)bs);
        atomicAdd(&g_npos, bn);
    }

    // ---- last block does the final combine ---------------------------------
    __shared__ int is_last;
    __threadfence();
    if (tid == 0) is_last = (atomicAdd(&g_ticket, 1u) == EPI_GRID - 1);
    __syncthreads();
    if (!is_last) return;

    float loss = 0.0f;
    int   nm = 0;
    for (int t = tid; t < NUM_T; t += EPI_BLK) {
        ull key = g_tkey[t];
        g_tkey[t] = 0ULL;                         // restore for next replay
        float tiou = __uint_as_float((unsigned)(key >> 32));
        if (tiou >= 0.5f) {
            nm++;
            unsigned aidx = 0xFFFFFFFFu - (unsigned)(key & 0xFFFFFFFFull);
            float4 ab = ((const float4*)anchors)[aidx];
            float4 tb = ((const float4*)tboxes)[t];
            float4 pr = ((const float4*)boxes_preds)[aidx];
            float bw = tb.z - tb.x, bh = tb.w - tb.y;
            float bcx = tb.x + 0.5f * bw, bcy = tb.y + 0.5f * bh;
            float aw = ab.z - ab.x, ah = ab.w - ab.y;
            float acx = ab.x + 0.5f * aw, acy = ab.y + 0.5f * ah;
            float tx = (bcx - acx) / aw;
            float ty = (bcy - acy) / ah;
            float tw = logf(fmaxf(bw, 1e-8f) / aw);
            float th = logf(fmaxf(bh, 1e-8f) / ah);
            loss += sl1(pr.x - tx) + sl1(pr.y - ty)
                  + sl1(pr.z - tw) + sl1(pr.w - th);
        }
    }
    #pragma unroll
    for (int o = 16; o > 0; o >>= 1) {
        loss += __shfl_down_sync(0xFFFFFFFFu, loss, o);
        nm   += __shfl_down_sync(0xFFFFFFFFu, nm,   o);
    }
    __shared__ float frs[8];
    __shared__ int   frm[8];
    if ((tid & 31) == 0) { frs[tid >> 5] = loss; frm[tid >> 5] = nm; }
    __syncthreads();
    if (tid == 0) {
        float total = 0.0f; int tm = 0;
        #pragma unroll
        for (int i = 0; i < 8; ++i) { total += frs[i]; tm += frm[i]; }
        double cls_total = atomicAdd(&g_cls_sum, 0.0);   // L2-coherent read
        int    npos      = atomicAdd(&g_npos, 0);
        double n_match   = (tm > 0) ? (double)tm : 1.0;
        double cls = cls_total / (double)npos;
        double reg = (double)total / (n_match * 4.0);
        out[0] = (float)(cls + reg);
        out[1] = (float)cls;
        out[2] = (float)reg;
        // restore scratch for next graph replay
        g_cls_sum = 0.0;
        g_npos    = 0;
        g_ticket  = 0u;
    }
}

// ---------------- launch -----------------------------------------------------
extern "C" void kernel_launch(void* const* d_in, const int* in_sizes, int n_in,
                              void* d_out, int out_size) {
    const float* cls_preds = (const float*)d_in[0];
    const float* box_preds = (const float*)d_in[1];
    const float* anchors   = (const float*)d_in[2];
    const float* tboxes    = (const float*)d_in[3];
    const int*   tlabels   = (const int*)d_in[4];
    float* out = (float*)d_out;

    fused_kernel<<<GRID, BLK>>>(anchors, tboxes, cls_preds);
    epilogue_kernel<<<EPI_GRID, EPI_BLK>>>(cls_preds, tlabels, box_preds,
                                           anchors, tboxes, out);
}

// round 5
// speedup vs baseline: 1.1803x; 1.1803x over previous
#include <cuda_runtime.h>
#include <cstdint>

#define NUM_A   98304
#define NUM_T   1024
#define NCLS    21
#define NLOGIT  (NUM_A * NCLS)
#define NVEC    (NLOGIT / 4)

#define GB      32                  // bins per dimension
#define CELLS   (GB * GB)

#define BLK     256
#define MATCHB  (NUM_A / BLK)       // 384 match blocks
#define FOCB    256                 // neg-focal blocks
#define FOC_THREADS (FOCB * BLK)

#define EPI_BLK  256
#define EPI_GRID (NUM_A / EPI_BLK)  // 384

typedef unsigned long long ull;

// ---------------- device scratch (zero-init; self-restoring across replays) --
__device__ float4   g_tsort_box[NUM_T];
__device__ float    g_tsort_area[NUM_T];
__device__ int      g_tsort_t[NUM_T];
__device__ int      g_off[CELLS + 1];
__device__ ull      g_akey[NUM_A];      // plain stores every run
__device__ ull      g_tkey[NUM_T];      // atomicMax; reset by last epi block
__device__ double   g_cls_sum;          // reset by last epi block
__device__ int      g_npos;             // reset by last epi block
__device__ unsigned g_ticket;           // reset by last epi block

// fast negative-class focal: 0.75 * sigmoid(x)^2 * softplus(x); 3 MUFU ops
__device__ __forceinline__ float focal_neg(float x) {
    float u = exp2f(x * 1.4426950408889634f);
    float d = u + 1.0f;
    float q; asm("rcp.approx.f32 %0, %1;" : "=f"(q) : "f"(d));
    float lg = __log2f(d);
    float p  = u * q;
    return (0.75f * 0.6931471805599453f) * (p * p) * lg;
}

// ---------------- prep: bucket targets into 32x32 spatial CSR ----------------
__global__ void __launch_bounds__(NUM_T) prep_kernel(
    const float* __restrict__ tboxes)
{
    __shared__ int cnt[CELLS];
    __shared__ int scn[CELLS];

    const int tid = threadIdx.x;
    cnt[tid] = 0;
    __syncthreads();

    float4 b = ((const float4*)tboxes)[tid];
    float cx = 0.5f * (b.x + b.z);
    float cy = 0.5f * (b.y + b.w);
    int bx = min(GB - 1, max(0, (int)(cx * (float)GB)));
    int by = min(GB - 1, max(0, (int)(cy * (float)GB)));
    int cell = by * GB + bx;
    int rank = atomicAdd(&cnt[cell], 1);
    __syncthreads();

    // Hillis-Steele inclusive scan over 1024 cells
    scn[tid] = cnt[tid];
    __syncthreads();
    #pragma unroll
    for (int off = 1; off < CELLS; off <<= 1) {
        int v = (tid >= off) ? scn[tid - off] : 0;
        __syncthreads();
        scn[tid] += v;
        __syncthreads();
    }

    g_off[tid] = scn[tid] - cnt[tid];      // exclusive offset
    if (tid == 0) g_off[CELLS] = NUM_T;

    int pos = scn[cell] - cnt[cell] + rank;
    g_tsort_box[pos]  = b;
    g_tsort_area[pos] = (b.z - b.x) * (b.w - b.y);
    g_tsort_t[pos]    = tid;
}

// ---------------- fused: windowed match + neg-focal blocks -------------------
__global__ void __launch_bounds__(BLK) fused_kernel(
    const float* __restrict__ anchors,
    const float* __restrict__ cls_preds)
{
    const int tid = threadIdx.x;

    if (blockIdx.x >= MATCHB) {
        // ---- negative focal over all logits (match-independent) ------------
        const int gt = (blockIdx.x - MATCHB) * BLK + tid;
        const float4* cp = (const float4*)cls_preds;
        float acc = 0.0f;
        for (int i = gt; i < NVEC; i += FOC_THREADS) {
            float4 v = cp[i];
            acc += focal_neg(v.x) + focal_neg(v.y)
                 + focal_neg(v.z) + focal_neg(v.w);
        }
        #pragma unroll
        for (int o = 16; o > 0; o >>= 1)
            acc += __shfl_down_sync(0xFFFFFFFFu, acc, o);
        __shared__ float rs[8];
        if ((tid & 31) == 0) rs[tid >> 5] = acc;
        __syncthreads();
        if (tid == 0) {
            float s = 0.0f;
            #pragma unroll
            for (int i = 0; i < 8; ++i) s += rs[i];
            atomicAdd(&g_cls_sum, (double)s);
        }
        return;
    }

    // ---- match block: 256 anchors, windowed candidate scan ------------------
    __shared__ float4 s_box[NUM_T];
    __shared__ float  s_area[NUM_T];
    __shared__ int    s_t[NUM_T];
    __shared__ int    s_off[CELLS + 1];

    for (int i = tid; i < NUM_T; i += BLK) {
        s_box[i]  = g_tsort_box[i];
        s_area[i] = g_tsort_area[i];
        s_t[i]    = g_tsort_t[i];
    }
    for (int i = tid; i < CELLS + 1; i += BLK) s_off[i] = g_off[i];
    __syncthreads();

    const int a = blockIdx.x * BLK + tid;
    const float4 ab = ((const float4*)anchors)[a];
    const float aw  = ab.z - ab.x;
    const float ah  = ab.w - ab.y;
    const float acx = 0.5f * (ab.x + ab.z);
    const float acy = 0.5f * (ab.y + ab.w);
    const float area_a = aw * ah;

    // IoU >= 0.45 requires |dc| <= 0.55*max(size) and max(size) <= min(size/0.45, 0.34)
    const float Rx = 0.55f * fminf(aw * 2.2223f, 0.34f);
    const float Ry = 0.55f * fminf(ah * 2.2223f, 0.34f);
    const int clo = max(0, (int)((acx - Rx) * (float)GB));
    const int chi = min(GB - 1, (int)((acx + Rx) * (float)GB));
    const int rlo = max(0, (int)((acy - Ry) * (float)GB));
    const int rhi = min(GB - 1, (int)((acy + Ry) * (float)GB));

    float bi = 0.0f, bS = 1.0f;
    int   bt = 0;

    for (int r = rlo; r <= rhi; ++r) {
        int i  = s_off[(r << 5) + clo];
        int ie = s_off[(r << 5) + chi + 1];
        for (; i < ie; ++i) {
            float4 tb = s_box[i];
            float lx = fmaxf(ab.x, tb.x), ly = fmaxf(ab.y, tb.y);
            float rx = fminf(ab.z, tb.z), ry = fminf(ab.w, tb.w);
            float w  = fmaxf(rx - lx, 0.0f);
            float inter = w * (ry - ly);          // neg h -> loses all tests
            float S = area_a + s_area[i];         // union = S - inter
            bool p = inter * bS > bi * S;         // cross-mult iou compare
            if (p) { bi = inter; bS = S; bt = s_t[i]; }
            if (inter > 0.3103448f * S) {         // iou > 0.45 (rare)
                float iou = __fdividef(inter, S - inter);
                ull key = ((ull)__float_as_uint(iou) << 32)
                        | (ull)(0xFFFFFFFFu - (unsigned)a);
                atomicMax(&g_tkey[bt == s_t[i] && p ? s_t[i] : s_t[i]], key);
            }
        }
    }

    float iou = __fdividef(bi, bS - bi);
    g_akey[a] = ((ull)__float_as_uint(iou) << 32)
              | (ull)(0xFFFFFFFFu - (unsigned)bt);
}

// ---------------- epilogue: pos-focal correction + final combine -------------
__device__ __forceinline__ float sl1(float d) {
    float ad = fabsf(d);
    return (ad < 1.0f) ? 0.5f * d * d : ad - 0.5f;
}

__global__ void __launch_bounds__(EPI_BLK) epilogue_kernel(
    const float* __restrict__ cls_preds,
    const int*   __restrict__ tlabels,
    const float* __restrict__ boxes_preds,
    const float* __restrict__ anchors,
    const float* __restrict__ tboxes,
    float* __restrict__ out)
{
    const int tid = threadIdx.x;
    const int a = blockIdx.x * EPI_BLK + tid;

    ull key = g_akey[a];
    float iou = __uint_as_float((unsigned)(key >> 32));
    float delta = 0.0f;
    int   np = 0;
    if (iou >= 0.5f) {
        np = 1;
        int t = (int)(0xFFFFFFFFu - (unsigned)(key & 0xFFFFFFFFull));
        int L = tlabels[t];
        float x = cls_preds[(size_t)a * NCLS + L];
        float ax = fabsf(x);
        float ce = fmaxf(x, 0.0f) - x + log1pf(expf(-ax));
        float p  = 1.0f / (1.0f + expf(-x));
        float om = 1.0f - p;
        delta = 0.25f * om * om * ce - focal_neg(x);
    }
    #pragma unroll
    for (int o = 16; o > 0; o >>= 1) {
        delta += __shfl_down_sync(0xFFFFFFFFu, delta, o);
        np    += __shfl_down_sync(0xFFFFFFFFu, np,    o);
    }
    __shared__ float rs[8];
    __shared__ int   ri[8];
    if ((tid & 31) == 0) { rs[tid >> 5] = delta; ri[tid >> 5] = np; }
    __syncthreads();
    if (tid == 0) {
        float bs = 0.0f; int bn = 0;
        #pragma unroll
        for (int i = 0; i < 8; ++i) { bs += rs[i]; bn += ri[i]; }
        atomicAdd(&g_cls_sum, (double)bs);
        atomicAdd(&g_npos, bn);
    }

    // ---- last block: regression loss + combine + scratch restore ------------
    __shared__ int is_last;
    __threadfence();
    if (tid == 0) is_last = (atomicAdd(&g_ticket, 1u) == EPI_GRID - 1);
    __syncthreads();
    if (!is_last) return;

    float loss = 0.0f;
    int   nm = 0;
    for (int t = tid; t < NUM_T; t += EPI_BLK) {
        ull k = g_tkey[t];
        g_tkey[t] = 0ULL;                          // restore for next replay
        float tiou = __uint_as_float((unsigned)(k >> 32));
        if (tiou >= 0.5f) {
            nm++;
            unsigned aidx = 0xFFFFFFFFu - (unsigned)(k & 0xFFFFFFFFull);
            float4 abx = ((const float4*)anchors)[aidx];
            float4 tb  = ((const float4*)tboxes)[t];
            float4 pr  = ((const float4*)boxes_preds)[aidx];
            float bw = tb.z - tb.x, bh = tb.w - tb.y;
            float bcx = tb.x + 0.5f * bw, bcy = tb.y + 0.5f * bh;
            float aw = abx.z - abx.x, ah = abx.w - abx.y;
            float acx = abx.x + 0.5f * aw, acy = abx.y + 0.5f * ah;
            float tx = (bcx - acx) / aw;
            float ty = (bcy - acy) / ah;
            float tw = logf(fmaxf(bw, 1e-8f) / aw);
            float th = logf(fmaxf(bh, 1e-8f) / ah);
            loss += sl1(pr.x - tx) + sl1(pr.y - ty)
                  + sl1(pr.z - tw) + sl1(pr.w - th);
        }
    }
    #pragma unroll
    for (int o = 16; o > 0; o >>= 1) {
        loss += __shfl_down_sync(0xFFFFFFFFu, loss, o);
        nm   += __shfl_down_sync(0xFFFFFFFFu, nm,   o);
    }
    __shared__ float frs[8];
    __shared__ int   frm[8];
    if ((tid & 31) == 0) { frs[tid >> 5] = loss; frm[tid >> 5] = nm; }
    __syncthreads();
    if (tid == 0) {
        float total = 0.0f; int tm = 0;
        #pragma unroll
        for (int i = 0; i < 8; ++i) { total += frs[i]; tm += frm[i]; }
        double cls_total = atomicAdd(&g_cls_sum, 0.0);
        int    npos      = atomicAdd(&g_npos, 0);
        double n_match   = (tm > 0) ? (double)tm : 1.0;
        double cls = cls_total / (double)npos;
        double reg = (double)total / (n_match * 4.0);
        out[0] = (float)(cls + reg);
        out[1] = (float)cls;
        out[2] = (float)reg;
        g_cls_sum = 0.0;
        g_npos    = 0;
        g_ticket  = 0u;
    }
}

// ---------------- launch -----------------------------------------------------
extern "C" void kernel_launch(void* const* d_in, const int* in_sizes, int n_in,
                              void* d_out, int out_size) {
    const float* cls_preds = (const float*)d_in[0];
    const float* box_preds = (const float*)d_in[1];
    const float* anchors   = (const float*)d_in[2];
    const float* tboxes    = (const float*)d_in[3];
    const int*   tlabels   = (const int*)d_in[4];
    float* out = (float*)d_out;

    prep_kernel<<<1, NUM_T>>>(tboxes);
    fused_kernel<<<MATCHB + FOCB, BLK>>>(anchors, cls_preds);
    epilogue_kernel<<<EPI_GRID, EPI_BLK>>>(cls_preds, tlabels, box_preds,
                                           anchors, tboxes, out);
}

// round 6
// speedup vs baseline: 1.2736x; 1.0790x over previous
#include <cuda_runtime.h>
#include <cstdint>

#define NUM_A   98304
#define NUM_T   1024
#define NCLS    21
#define NLOGIT  (NUM_A * NCLS)
#define NVEC    (NLOGIT / 4)

#define GB      32
#define CELLS   (GB * GB)

#define BLK     256
#define MATCHB  (NUM_A / BLK)       // 384
#define FOCB    256
#define FOC_THREADS (FOCB * BLK)

#define EPI_BLK  256
#define EPI_GRID (NUM_A / EPI_BLK)  // 384

typedef unsigned long long ull;

// ---------------- device scratch (zero-init; self-restoring) -----------------
__device__ float4   g_tbox_s[NUM_T];
__device__ float    g_tarea_s[NUM_T];
__device__ int      g_tid_s[NUM_T];
__device__ int      g_toff[CELLS + 1];

__device__ int      g_acnt[CELLS];      // reset by last epi block
__device__ int      g_aoff[CELLS + 1];
__device__ int      g_acell[NUM_A];
__device__ int      g_arank[NUM_A];
__device__ float4   g_abox_s[NUM_A];
__device__ int      g_aid_s[NUM_A];

__device__ ull      g_akey[NUM_A];      // plain stores each run
__device__ ull      g_tkey[NUM_T];      // atomicMax; reset by last epi block
__device__ double   g_cls_sum;          // reset by last epi block
__device__ int      g_npos;             // reset by last epi block
__device__ unsigned g_ticket;           // reset by last epi block

// fast negative-class focal: 0.75 * sigmoid(x)^2 * softplus(x); 3 MUFU ops
__device__ __forceinline__ float focal_neg(float x) {
    float u = exp2f(x * 1.4426950408889634f);
    float d = u + 1.0f;
    float q; asm("rcp.approx.f32 %0, %1;" : "=f"(q) : "f"(d));
    float lg = __log2f(d);
    float p  = u * q;
    return (0.75f * 0.6931471805599453f) * (p * p) * lg;
}

__device__ __forceinline__ int cell_of(float cx, float cy) {
    int bx = min(GB - 1, max(0, (int)(cx * (float)GB)));
    int by = min(GB - 1, max(0, (int)(cy * (float)GB)));
    return by * GB + bx;
}

// fast 1024-thread inclusive scan (3-phase shfl), returns inclusive value
__device__ __forceinline__ int scan1024(int v, int tid, int* wsum) {
    int lane = tid & 31, wid = tid >> 5;
    #pragma unroll
    for (int o = 1; o < 32; o <<= 1) {
        int n = __shfl_up_sync(0xFFFFFFFFu, v, o);
        if (lane >= o) v += n;
    }
    if (lane == 31) wsum[wid] = v;
    __syncthreads();
    if (wid == 0) {
        int s = wsum[lane];
        #pragma unroll
        for (int o = 1; o < 32; o <<= 1) {
            int n = __shfl_up_sync(0xFFFFFFFFu, s, o);
            if (lane >= o) s += n;
        }
        wsum[lane] = s;
    }
    __syncthreads();
    return v + (wid > 0 ? wsum[wid - 1] : 0);
}

// ---------------- L1: anchor cell + rank -------------------------------------
__global__ void __launch_bounds__(BLK) acount_kernel(
    const float* __restrict__ anchors)
{
    const int a = blockIdx.x * BLK + threadIdx.x;
    float4 ab = ((const float4*)anchors)[a];
    int cell = cell_of(0.5f * (ab.x + ab.z), 0.5f * (ab.y + ab.w));
    g_acell[a] = cell;
    g_arank[a] = atomicAdd(&g_acnt[cell], 1);
}

// ---------------- L2: target CSR + anchor offset scan (1 block) --------------
__global__ void __launch_bounds__(NUM_T) prep_kernel(
    const float* __restrict__ tboxes)
{
    __shared__ int tcnt[CELLS];
    __shared__ int wsum[32];
    const int tid = threadIdx.x;

    tcnt[tid] = 0;
    __syncthreads();

    float4 b = ((const float4*)tboxes)[tid];
    int cell = cell_of(0.5f * (b.x + b.z), 0.5f * (b.y + b.w));
    int rank = atomicAdd(&tcnt[cell], 1);
    __syncthreads();

    int incl = scan1024(tcnt[tid], tid, wsum);
    int excl = incl - tcnt[tid];
    g_toff[tid] = excl;
    if (tid == 0) g_toff[CELLS] = NUM_T;
    __syncthreads();
    __shared__ int texcl[CELLS];
    texcl[tid] = excl;
    __syncthreads();
    int pos = texcl[cell] + rank;
    g_tbox_s[pos]  = b;
    g_tarea_s[pos] = (b.z - b.x) * (b.w - b.y);
    g_tid_s[pos]   = tid;

    // anchor offsets
    __syncthreads();
    int ai = scan1024(g_acnt[tid], tid, wsum);
    g_aoff[tid] = ai - g_acnt[tid];
    if (tid == 0) g_aoff[CELLS] = NUM_A;
}

// ---------------- L3: anchor scatter -----------------------------------------
__global__ void __launch_bounds__(BLK) ascatter_kernel(
    const float* __restrict__ anchors)
{
    const int a = blockIdx.x * BLK + threadIdx.x;
    int pos = g_aoff[g_acell[a]] + g_arank[a];
    g_abox_s[pos] = ((const float4*)anchors)[a];
    g_aid_s[pos]  = a;
}

// ---------------- L4: fused windowed match (sorted anchors) + neg-focal ------
__global__ void __launch_bounds__(BLK) fused_kernel(
    const float* __restrict__ cls_preds)
{
    const int tid = threadIdx.x;

    if (blockIdx.x >= MATCHB) {
        const int gt = (blockIdx.x - MATCHB) * BLK + tid;
        const float4* cp = (const float4*)cls_preds;
        float acc = 0.0f;
        for (int i = gt; i < NVEC; i += FOC_THREADS) {
            float4 v = cp[i];
            acc += focal_neg(v.x) + focal_neg(v.y)
                 + focal_neg(v.z) + focal_neg(v.w);
        }
        #pragma unroll
        for (int o = 16; o > 0; o >>= 1)
            acc += __shfl_down_sync(0xFFFFFFFFu, acc, o);
        __shared__ float rs[8];
        if ((tid & 31) == 0) rs[tid >> 5] = acc;
        __syncthreads();
        if (tid == 0) {
            float s = 0.0f;
            #pragma unroll
            for (int i = 0; i < 8; ++i) s += rs[i];
            atomicAdd(&g_cls_sum, (double)s);
        }
        return;
    }

    __shared__ float4 s_box[NUM_T];
    __shared__ float  s_area[NUM_T];
    __shared__ int    s_t[NUM_T];
    __shared__ int    s_off[CELLS + 1];

    for (int i = tid; i < NUM_T; i += BLK) {
        s_box[i]  = g_tbox_s[i];
        s_area[i] = g_tarea_s[i];
        s_t[i]    = g_tid_s[i];
    }
    for (int i = tid; i < CELLS + 1; i += BLK) s_off[i] = g_toff[i];
    __syncthreads();

    const int sp   = blockIdx.x * BLK + tid;      // sorted position
    const float4 ab = g_abox_s[sp];
    const int   orig = g_aid_s[sp];
    const float aw  = ab.z - ab.x;
    const float ah  = ab.w - ab.y;
    const float acx = 0.5f * (ab.x + ab.z);
    const float acy = 0.5f * (ab.y + ab.w);
    const float area_a = aw * ah;

    const float Rx = 0.55f * fminf(aw * 2.2223f, 0.34f);
    const float Ry = 0.55f * fminf(ah * 2.2223f, 0.34f);
    int clo = max(0, (int)((acx - Rx) * (float)GB));
    int chi = min(GB - 1, (int)((acx + Rx) * (float)GB));
    int rlo = max(0, (int)((acy - Ry) * (float)GB));
    int rhi = min(GB - 1, (int)((acy + Ry) * (float)GB));

    // warp-union window: sorted anchors are spatially coherent, so union ~ own
    int clo_w = __reduce_min_sync(0xFFFFFFFFu, (unsigned)clo);
    int chi_w = __reduce_max_sync(0xFFFFFFFFu, (unsigned)chi);
    int rlo_w = __reduce_min_sync(0xFFFFFFFFu, (unsigned)rlo);
    int rhi_w = __reduce_max_sync(0xFFFFFFFFu, (unsigned)rhi);

    float bi = 0.0f, bS = 1.0f;
    int   bt = 0;

    for (int r = rlo_w; r <= rhi_w; ++r) {
        int i  = s_off[(r << 5) + clo_w];
        int ie = s_off[(r << 5) + chi_w + 1];
        for (; i < ie; ++i) {
            float4 tb = s_box[i];
            float lx = fmaxf(ab.x, tb.x), ly = fmaxf(ab.y, tb.y);
            float rx = fminf(ab.z, tb.z), ry = fminf(ab.w, tb.w);
            float w  = fmaxf(rx - lx, 0.0f);
            float inter = w * (ry - ly);          // neg h loses all tests
            float S = area_a + s_area[i];         // union = S - inter
            bool p = inter * bS > bi * S;
            if (p) { bi = inter; bS = S; bt = s_t[i]; }
            if (inter > 0.3103448f * S) {         // iou > 0.45, rare
                float iou = __fdividef(inter, S - inter);
                ull key = ((ull)__float_as_uint(iou) << 32)
                        | (ull)(0xFFFFFFFFu - (unsigned)orig);
                atomicMax(&g_tkey[s_t[i]], key);
            }
        }
    }

    float iou = __fdividef(bi, bS - bi);
    g_akey[orig] = ((ull)__float_as_uint(iou) << 32)
                 | (ull)(0xFFFFFFFFu - (unsigned)bt);
}

// ---------------- L5: epilogue -----------------------------------------------
__device__ __forceinline__ float sl1(float d) {
    float ad = fabsf(d);
    return (ad < 1.0f) ? 0.5f * d * d : ad - 0.5f;
}

__global__ void __launch_bounds__(EPI_BLK) epilogue_kernel(
    const float* __restrict__ cls_preds,
    const int*   __restrict__ tlabels,
    const float* __restrict__ boxes_preds,
    const float* __restrict__ anchors,
    const float* __restrict__ tboxes,
    float* __restrict__ out)
{
    const int tid = threadIdx.x;
    const int a = blockIdx.x * EPI_BLK + tid;

    ull key = g_akey[a];
    float iou = __uint_as_float((unsigned)(key >> 32));
    float delta = 0.0f;
    int   np = 0;
    if (iou >= 0.5f) {
        np = 1;
        int t = (int)(0xFFFFFFFFu - (unsigned)(key & 0xFFFFFFFFull));
        int L = tlabels[t];
        float x = cls_preds[(size_t)a * NCLS + L];
        float ax = fabsf(x);
        float ce = fmaxf(x, 0.0f) - x + log1pf(expf(-ax));
        float p  = 1.0f / (1.0f + expf(-x));
        float om = 1.0f - p;
        delta = 0.25f * om * om * ce - focal_neg(x);
    }
    #pragma unroll
    for (int o = 16; o > 0; o >>= 1) {
        delta += __shfl_down_sync(0xFFFFFFFFu, delta, o);
        np    += __shfl_down_sync(0xFFFFFFFFu, np,    o);
    }
    __shared__ float rs[8];
    __shared__ int   ri[8];
    if ((tid & 31) == 0) { rs[tid >> 5] = delta; ri[tid >> 5] = np; }
    __syncthreads();
    if (tid == 0) {
        float bs = 0.0f; int bn = 0;
        #pragma unroll
        for (int i = 0; i < 8; ++i) { bs += rs[i]; bn += ri[i]; }
        atomicAdd(&g_cls_sum, (double)bs);
        atomicAdd(&g_npos, bn);
    }

    __shared__ int is_last;
    __threadfence();
    if (tid == 0) is_last = (atomicAdd(&g_ticket, 1u) == EPI_GRID - 1);
    __syncthreads();
    if (!is_last) return;

    // restore anchor-count scratch for next replay
    for (int i = tid; i < CELLS; i += EPI_BLK) g_acnt[i] = 0;

    float loss = 0.0f;
    int   nm = 0;
    for (int t = tid; t < NUM_T; t += EPI_BLK) {
        ull k = g_tkey[t];
        g_tkey[t] = 0ULL;
        float tiou = __uint_as_float((unsigned)(k >> 32));
        if (tiou >= 0.5f) {
            nm++;
            unsigned aidx = 0xFFFFFFFFu - (unsigned)(k & 0xFFFFFFFFull);
            float4 abx = ((const float4*)anchors)[aidx];
            float4 tb  = ((const float4*)tboxes)[t];
            float4 pr  = ((const float4*)boxes_preds)[aidx];
            float bw = tb.z - tb.x, bh = tb.w - tb.y;
            float bcx = tb.x + 0.5f * bw, bcy = tb.y + 0.5f * bh;
            float aw = abx.z - abx.x, ah = abx.w - abx.y;
            float acx = abx.x + 0.5f * aw, acy = abx.y + 0.5f * ah;
            float tx = (bcx - acx) / aw;
            float ty = (bcy - acy) / ah;
            float tw = logf(fmaxf(bw, 1e-8f) / aw);
            float th = logf(fmaxf(bh, 1e-8f) / ah);
            loss += sl1(pr.x - tx) + sl1(pr.y - ty)
                  + sl1(pr.z - tw) + sl1(pr.w - th);
        }
    }
    #pragma unroll
    for (int o = 16; o > 0; o >>= 1) {
        loss += __shfl_down_sync(0xFFFFFFFFu, loss, o);
        nm   += __shfl_down_sync(0xFFFFFFFFu, nm,   o);
    }
    __shared__ float frs[8];
    __shared__ int   frm[8];
    if ((tid & 31) == 0) { frs[tid >> 5] = loss; frm[tid >> 5] = nm; }
    __syncthreads();
    if (tid == 0) {
        float total = 0.0f; int tm = 0;
        #pragma unroll
        for (int i = 0; i < 8; ++i) { total += frs[i]; tm += frm[i]; }
        double cls_total = atomicAdd(&g_cls_sum, 0.0);
        int    npos      = atomicAdd(&g_npos, 0);
        double n_match   = (tm > 0) ? (double)tm : 1.0;
        double cls = cls_total / (double)npos;
        double reg = (double)total / (n_match * 4.0);
        out[0] = (float)(cls + reg);
        out[1] = (float)cls;
        out[2] = (float)reg;
        g_cls_sum = 0.0;
        g_npos    = 0;
        g_ticket  = 0u;
    }
}

// ---------------- launch -----------------------------------------------------
extern "C" void kernel_launch(void* const* d_in, const int* in_sizes, int n_in,
                              void* d_out, int out_size) {
    const float* cls_preds = (const float*)d_in[0];
    const float* box_preds = (const float*)d_in[1];
    const float* anchors   = (const float*)d_in[2];
    const float* tboxes    = (const float*)d_in[3];
    const int*   tlabels   = (const int*)d_in[4];
    float* out = (float*)d_out;

    acount_kernel<<<MATCHB, BLK>>>(anchors);
    prep_kernel<<<1, NUM_T>>>(tboxes);
    ascatter_kernel<<<MATCHB, BLK>>>(anchors);
    fused_kernel<<<MATCHB + FOCB, BLK>>>(cls_preds);
    epilogue_kernel<<<EPI_GRID, EPI_BLK>>>(cls_preds, tlabels, box_preds,
                                           anchors, tboxes, out);
}